// round 13
// baseline (speedup 1.0000x reference)
#include <cuda_runtime.h>
#include <cuda_bf16.h>
#include <math.h>
#include <stdint.h>

#define MAXN 100000
#define MAXE 1600000
#define D 64
#define K_PAD 208
#define C_TOT 256      // cols: [0:64) r, [64:128) i, [128:192) i_n, [192:256) h_n
#define TILE_N 64
#define NTHREADS 1024
#define GRID_SM 148
#define XSTR 68

// smem partition for node_kernel (floats)
#define OFF_MG 0
#define OFF_MI 24832
#define OFF_MH 33152
#define OFF_UB 37248
#define SMEM_FLOATS 53632   // 214,528 bytes

// ---------------- scratch ----------------
__device__ float g_S[2 * (size_t)MAXN * D];
__device__ float g_s[2 * MAXN];
__device__ float g_M[K_PAD * C_TOT];
__device__ float g_bias[C_TOT];
__device__ int   g_cnt[2 * MAXN];
__device__ int   g_off[2 * MAXN];       // after scan: exclusive offsets; after fill: segment ends
__device__ int   g_bsum[256];
__device__ int2  g_csr[2 * (size_t)MAXE];  // (src, w_bits) — 25.6 MB, L2-resident

// ---------------- kernel 1: precompute fused matrix ----------------
__global__ void precompute_kernel(const float* __restrict__ W_in, const float* __restrict__ b_in,
                                  const float* __restrict__ W_out, const float* __restrict__ b_out,
                                  const float* __restrict__ W_ih, const float* __restrict__ b_ih,
                                  const float* __restrict__ W_hh, const float* __restrict__ b_hh) {
    int k = blockIdx.x;
    int c = threadIdx.x;
    float v = 0.f;
    if (k < 64) {
        if (c < 192) {
            float a = 0.f;
            #pragma unroll 8
            for (int t = 0; t < 64; t++) a += W_in[k * 64 + t] * W_ih[t * 192 + c];
            v = a;
        }
    } else if (k < 128) {
        if (c < 192) {
            int aa = k - 64;
            float a = 0.f;
            #pragma unroll 8
            for (int t = 0; t < 64; t++) a += W_out[aa * 64 + t] * W_ih[(64 + t) * 192 + c];
            v = a;
        }
    } else if (k < 192) {
        int aa = k - 128;
        if (c < 128) v = W_hh[aa * 192 + c];
        else if (c >= 192) v = W_hh[aa * 192 + 128 + (c - 192)];
    } else if (k == 192) {
        if (c < 192) {
            float a = 0.f;
            for (int t = 0; t < 64; t++) a += b_in[t] * W_ih[t * 192 + c];
            v = a;
        }
    } else if (k == 193) {
        if (c < 192) {
            float a = 0.f;
            for (int t = 0; t < 64; t++) a += b_out[t] * W_ih[(64 + t) * 192 + c];
            v = a;
        }
    }
    g_M[k * C_TOT + c] = v;
    if (k == 0) {
        float b;
        if (c < 128)      b = b_ih[c] + b_hh[c];
        else if (c < 192) b = b_ih[c];
        else              b = b_hh[c - 64];
        g_bias[c] = b;
    }
}

// ---------------- CSR build ----------------
__global__ void zero_cnt_kernel(int nseg) {
    int i = blockIdx.x * blockDim.x + threadIdx.x;
    if (i < nseg) g_cnt[i] = 0;
}

__global__ void hist_kernel(const int* __restrict__ dstA, const int* __restrict__ dstB,
                            int E, int n) {
    int set = blockIdx.y;
    const int* dst = set ? dstB : dstA;
    int base = set * n;
    for (int e = blockIdx.x * blockDim.x + threadIdx.x; e < E; e += gridDim.x * blockDim.x)
        atomicAdd(&g_cnt[base + dst[e]], 1);
}

__global__ void scan1_kernel(int nseg) {
    __shared__ int sh[1024];
    int tid = threadIdx.x;
    int g = blockIdx.x * 1024 + tid;
    int x = (g < nseg) ? g_cnt[g] : 0;
    sh[tid] = x;
    __syncthreads();
    #pragma unroll
    for (int o = 1; o < 1024; o <<= 1) {
        int v = (tid >= o) ? sh[tid - o] : 0;
        __syncthreads();
        sh[tid] += v;
        __syncthreads();
    }
    if (g < nseg) g_off[g] = sh[tid] - x;     // exclusive
    if (tid == 1023) g_bsum[blockIdx.x] = sh[1023];
}

// parallel exclusive scan over <=256 block sums (single block)
__global__ void scan2_kernel(int nblocks) {
    __shared__ int sh[256];
    int tid = threadIdx.x;
    int x = (tid < nblocks) ? g_bsum[tid] : 0;
    sh[tid] = x;
    __syncthreads();
    #pragma unroll
    for (int o = 1; o < 256; o <<= 1) {
        int v = (tid >= o) ? sh[tid - o] : 0;
        __syncthreads();
        sh[tid] += v;
        __syncthreads();
    }
    if (tid < nblocks) g_bsum[tid] = sh[tid] - x;   // exclusive
}

__global__ void scan3_kernel(int nseg) {
    int g = blockIdx.x * 1024 + threadIdx.x;
    if (g < nseg) g_off[g] += g_bsum[blockIdx.x];
}

__global__ void fill_kernel(const int* __restrict__ srcA, const int* __restrict__ dstA,
                            const float* __restrict__ wA,
                            const int* __restrict__ srcB, const int* __restrict__ dstB,
                            const float* __restrict__ wB,
                            int E, int n) {
    int set = blockIdx.y;
    const int*   src = set ? srcB : srcA;
    const int*   dst = set ? dstB : dstA;
    const float* wp  = set ? wB   : wA;
    int base = set * n;
    for (int e = blockIdx.x * blockDim.x + threadIdx.x; e < E; e += gridDim.x * blockDim.x) {
        int pos = atomicAdd(&g_off[base + dst[e]], 1);
        g_csr[pos] = make_int2(src[e], __float_as_int(wp[e]));
    }
}

// ---------------- gather: atomic-free segment sums ----------------
// Half-warp (16 lanes, float4 each) per segment; writes S and s directly.
__global__ void gather_kernel(const float4* __restrict__ h4, int nseg) {
    int l   = threadIdx.x & 15;
    int hw  = (blockIdx.x * blockDim.x + threadIdx.x) >> 4;
    int nhw = (gridDim.x * blockDim.x) >> 4;

    for (int s = hw; s < nseg; s += nhw) {
        int end = g_off[s];              // after fill: end of segment
        int cnt = g_cnt[s];
        const int2* bp = g_csr + (end - cnt);
        float4 acc = make_float4(0.f, 0.f, 0.f, 0.f);
        float ws = 0.f;
        #pragma unroll 4
        for (int e = 0; e < cnt; e++) {
            int2 ed = __ldg(bp + e);
            float w = __int_as_float(ed.y);
            float4 v = h4[(size_t)ed.x * 16 + l];
            acc.x += v.x * w; acc.y += v.y * w; acc.z += v.z * w; acc.w += v.w * w;
            ws += w;
        }
        reinterpret_cast<float4*>(g_S)[(size_t)s * 16 + l] = acc;
        if (l == 0) g_s[s] = ws;
    }
}

__device__ __forceinline__ float fsig(float x) { return 1.f / (1.f + __expf(-x)); }
__device__ __forceinline__ float ftanh(float x) { return 2.f / (1.f + __expf(-2.f * x)) - 1.f; }

// one k-step: 32 FFMA, 8 nodes x 4 cols
__device__ __forceinline__ void step84(float acc[8][4], const float* mp, const float* xp) {
    float4 m  = *reinterpret_cast<const float4*>(mp);
    float4 xa = *reinterpret_cast<const float4*>(xp);
    float4 xb = *reinterpret_cast<const float4*>(xp + 4);
    acc[0][0]+=xa.x*m.x; acc[0][1]+=xa.x*m.y; acc[0][2]+=xa.x*m.z; acc[0][3]+=xa.x*m.w;
    acc[1][0]+=xa.y*m.x; acc[1][1]+=xa.y*m.y; acc[1][2]+=xa.y*m.z; acc[1][3]+=xa.y*m.w;
    acc[2][0]+=xa.z*m.x; acc[2][1]+=xa.z*m.y; acc[2][2]+=xa.z*m.z; acc[2][3]+=xa.z*m.w;
    acc[3][0]+=xa.w*m.x; acc[3][1]+=xa.w*m.y; acc[3][2]+=xa.w*m.z; acc[3][3]+=xa.w*m.w;
    acc[4][0]+=xb.x*m.x; acc[4][1]+=xb.x*m.y; acc[4][2]+=xb.x*m.z; acc[4][3]+=xb.x*m.w;
    acc[5][0]+=xb.y*m.x; acc[5][1]+=xb.y*m.y; acc[5][2]+=xb.y*m.z; acc[5][3]+=xb.y*m.w;
    acc[6][0]+=xb.z*m.x; acc[6][1]+=xb.z*m.y; acc[6][2]+=xb.z*m.z; acc[6][3]+=xb.z*m.w;
    acc[7][0]+=xb.w*m.x; acc[7][1]+=xb.w*m.y; acc[7][2]+=xb.w*m.z; acc[7][3]+=xb.w*m.w;
}

// ---------------- node kernel (unchanged from R10) ----------------
extern __shared__ float smem[];

__global__ __launch_bounds__(NTHREADS, 1) void node_kernel(const float* __restrict__ hidden,
                                                           float* __restrict__ out,
                                                           int n_nodes, int ntiles) {
    float* Mg = smem + OFF_MG;
    float* Mi = smem + OFF_MI;
    float* Mh = smem + OFF_MH;
    float* UB = smem + OFF_UB;

    int tid = threadIdx.x;
    int wid = tid >> 5;
    int lane = tid & 31;

    {
        float4* Mg4 = reinterpret_cast<float4*>(Mg);
        for (int i = tid; i < 194 * 32; i += NTHREADS) {
            int r = i >> 5, c4 = i & 31;
            Mg4[i] = *reinterpret_cast<const float4*>(&g_M[r * C_TOT + c4 * 4]);
        }
        float4* Mi4 = reinterpret_cast<float4*>(Mi);
        for (int i = tid; i < 130 * 16; i += NTHREADS) {
            int r = i >> 4, c4 = i & 15;
            int gr = (r < 128) ? r : (192 + (r - 128));
            Mi4[i] = *reinterpret_cast<const float4*>(&g_M[gr * C_TOT + 128 + c4 * 4]);
        }
        float4* Mh4 = reinterpret_cast<float4*>(Mh);
        for (int i = tid; i < 64 * 16; i += NTHREADS) {
            int r = i >> 4, c4 = i & 15;
            Mh4[i] = *reinterpret_cast<const float4*>(&g_M[(128 + r) * C_TOT + 192 + c4 * 4]);
        }
    }
    __syncthreads();

    const float* Sin  = g_S;
    const float* Sout = g_S + (size_t)n_nodes * D;

    int kh, ng, colb;
    if (wid < 16)      { kh = wid >> 3;        ng = wid & 7;                        colb = lane * 4; }
    else if (wid < 24) { kh = (wid - 16) >> 2; ng = ((wid - 16) & 3) * 2 + (lane >> 4); colb = 128 + (lane & 15) * 4; }
    else               { kh = (wid - 24) >> 2; ng = ((wid - 24) & 3) * 2 + (lane >> 4); colb = 192 + (lane & 15) * 4; }

    for (int tile = blockIdx.x; tile < ntiles; tile += gridDim.x) {
        int node0 = tile * TILE_N;

        {
            int g = tid >> 4;
            int l = tid & 15;
            int n = node0 + g;
            bool nv = (n < n_nodes);
            #pragma unroll
            for (int k = l; k < 194; k += 16) {
                float v = 0.f;
                if (nv) {
                    if (k < 64)        v = Sin[(size_t)n * D + k];
                    else if (k < 128)  v = Sout[(size_t)n * D + (k - 64)];
                    else if (k < 192)  v = hidden[(size_t)n * D + (k - 128)];
                    else if (k == 192) v = g_s[n];
                    else               v = g_s[n_nodes + n];
                }
                UB[k * XSTR + g] = v;
            }
        }
        __syncthreads();

        float acc[8][4];
        if (kh == 0) {
            float4 bv = *reinterpret_cast<const float4*>(&g_bias[colb]);
            #pragma unroll
            for (int i = 0; i < 8; i++) { acc[i][0]=bv.x; acc[i][1]=bv.y; acc[i][2]=bv.z; acc[i][3]=bv.w; }
        } else {
            #pragma unroll
            for (int i = 0; i < 8; i++) { acc[i][0]=0.f; acc[i][1]=0.f; acc[i][2]=0.f; acc[i][3]=0.f; }
        }

        if (wid < 16) {
            const float* mp = Mg + (kh * 97) * 128 + colb;
            const float* xp = UB + (kh * 97) * XSTR + ng * 8;
            #pragma unroll 2
            for (int k = 0; k < 97; k++) {
                step84(acc, mp, xp);
                mp += 128; xp += XSTR;
            }
        } else if (wid < 24) {
            if (kh == 0) {
                const float* mp = Mi + (colb - 128);
                const float* xp = UB + ng * 8;
                #pragma unroll 2
                for (int k = 0; k < 65; k++) {
                    step84(acc, mp, xp);
                    mp += 64; xp += XSTR;
                }
            } else {
                const float* mp = Mi + 65 * 64 + (colb - 128);
                const float* xp = UB + 65 * XSTR + ng * 8;
                #pragma unroll 2
                for (int k = 0; k < 63; k++) {
                    step84(acc, mp, xp);
                    mp += 64; xp += XSTR;
                }
                step84(acc, mp, UB + 192 * XSTR + ng * 8);
                step84(acc, mp + 64, UB + 193 * XSTR + ng * 8);
            }
        } else {
            const float* mp = Mh + (kh * 32) * 64 + (colb - 192);
            const float* xp = UB + (128 + kh * 32) * XSTR + ng * 8;
            #pragma unroll 2
            for (int k = 0; k < 32; k++) {
                step84(acc, mp, xp);
                mp += 64; xp += XSTR;
            }
        }
        __syncthreads();

        if (kh == 1) {
            #pragma unroll
            for (int i = 0; i < 8; i++)
                *reinterpret_cast<float4*>(&UB[(ng * 8 + i) * C_TOT + colb]) =
                    make_float4(acc[i][0], acc[i][1], acc[i][2], acc[i][3]);
        }
        __syncthreads();
        if (kh == 0) {
            #pragma unroll
            for (int i = 0; i < 8; i++) {
                float4* p = reinterpret_cast<float4*>(&UB[(ng * 8 + i) * C_TOT + colb]);
                float4 v = *p;
                v.x += acc[i][0]; v.y += acc[i][1]; v.z += acc[i][2]; v.w += acc[i][3];
                *p = v;
            }
        }
        __syncthreads();

        #pragma unroll
        for (int j = 0; j < 4; j++) {
            int o = tid + j * NTHREADS;
            int i = o >> 6;
            int a = o & 63;
            int n = node0 + i;
            if (n < n_nodes) {
                float gr   = UB[i * C_TOT + a];
                float gi   = UB[i * C_TOT + 64 + a];
                float g_in = UB[i * C_TOT + 128 + a];
                float g_hn = UB[i * C_TOT + 192 + a];
                float r  = fsig(gr);
                float ig = fsig(gi);
                float newg = ftanh(g_in + r * g_hn);
                float h = hidden[(size_t)n * D + a];
                out[(size_t)n * D + a] = (1.f - ig) * h + ig * newg;
            }
        }
        __syncthreads();
    }
}

// ---------------- launch ----------------
extern "C" void kernel_launch(void* const* d_in, const int* in_sizes, int n_in,
                              void* d_out, int out_size) {
    const float* hidden  = (const float*)d_in[0];
    const int*   in_src  = (const int*)  d_in[1];
    const int*   in_dst  = (const int*)  d_in[2];
    const float* in_w    = (const float*)d_in[3];
    const int*   out_src = (const int*)  d_in[4];
    const int*   out_dst = (const int*)  d_in[5];
    const float* out_w   = (const float*)d_in[6];
    const float* W_in    = (const float*)d_in[7];
    const float* b_in    = (const float*)d_in[8];
    const float* W_out   = (const float*)d_in[9];
    const float* b_out   = (const float*)d_in[10];
    const float* W_ih    = (const float*)d_in[11];
    const float* b_ih    = (const float*)d_in[12];
    const float* W_hh    = (const float*)d_in[13];
    const float* b_hh    = (const float*)d_in[14];
    float* out = (float*)d_out;

    int n = in_sizes[0] / D;
    if (n > MAXN) n = MAXN;
    int E = in_sizes[1];
    if (E > MAXE) E = MAXE;

    int nseg = 2 * n;
    int sblk = (nseg + 1023) / 1024;     // <= 196

    precompute_kernel<<<K_PAD, C_TOT>>>(W_in, b_in, W_out, b_out, W_ih, b_ih, W_hh, b_hh);

    // CSR build
    zero_cnt_kernel<<<sblk, 1024>>>(nseg);
    if (E > 0) {
        dim3 hgrid(592, 2);
        hist_kernel<<<hgrid, 256>>>(in_dst, out_dst, E, n);
    }
    scan1_kernel<<<sblk, 1024>>>(nseg);
    scan2_kernel<<<1, 256>>>(sblk);
    scan3_kernel<<<sblk, 1024>>>(nseg);
    if (E > 0) {
        dim3 fgrid(592, 2);
        fill_kernel<<<fgrid, 256>>>(in_src, in_dst, in_w, out_src, out_dst, out_w, E, n);
    }

    // atomic-free gather
    gather_kernel<<<1184, 256>>>((const float4*)hidden, nseg);

    // fused node GEMM + GRU
    int ntiles = (n + TILE_N - 1) / TILE_N;
    int grid_n = ntiles < GRID_SM ? ntiles : GRID_SM;
    size_t smem_bytes = (size_t)SMEM_FLOATS * sizeof(float);
    cudaFuncSetAttribute(node_kernel, cudaFuncAttributeMaxDynamicSharedMemorySize,
                         (int)smem_bytes);
    node_kernel<<<grid_n, NTHREADS, smem_bytes>>>(hidden, out, n, ntiles);
}

// round 14
// speedup vs baseline: 1.0792x; 1.0792x over previous
#include <cuda_runtime.h>
#include <cuda_bf16.h>
#include <math.h>
#include <stdint.h>

#define MAXN 100000
#define MAXE 1600000
#define D 64
#define K_PAD 208
#define C_TOT 256      // cols: [0:64) r, [64:128) i, [128:192) i_n, [192:256) h_n
#define TILE_N 64
#define NTHREADS 1024
#define GRID_SM 148
#define XSTR 68

// smem partition for node_kernel (floats)
#define OFF_MG 0
#define OFF_MI 24832
#define OFF_MH 33152
#define OFF_UB 37248
#define SMEM_FLOATS 53632   // 214,528 bytes

// ---------------- scratch ----------------
__device__ float g_S[2 * (size_t)MAXN * D];
__device__ float g_s[2 * MAXN];
__device__ float g_M[K_PAD * C_TOT];
__device__ float g_bias[C_TOT];
__device__ int   g_cnt[2 * MAXN];
__device__ int   g_off[2 * MAXN];       // after scan: exclusive offsets; after fill: segment ends
__device__ int   g_bsum[256];
__device__ int2  g_csr[2 * (size_t)MAXE];  // (src, w_bits) — 25.6 MB, L2-resident

// ---------------- kernel 1: precompute fused matrix ----------------
__global__ void precompute_kernel(const float* __restrict__ W_in, const float* __restrict__ b_in,
                                  const float* __restrict__ W_out, const float* __restrict__ b_out,
                                  const float* __restrict__ W_ih, const float* __restrict__ b_ih,
                                  const float* __restrict__ W_hh, const float* __restrict__ b_hh) {
    int k = blockIdx.x;
    int c = threadIdx.x;
    float v = 0.f;
    if (k < 64) {
        if (c < 192) {
            float a = 0.f;
            #pragma unroll 8
            for (int t = 0; t < 64; t++) a += W_in[k * 64 + t] * W_ih[t * 192 + c];
            v = a;
        }
    } else if (k < 128) {
        if (c < 192) {
            int aa = k - 64;
            float a = 0.f;
            #pragma unroll 8
            for (int t = 0; t < 64; t++) a += W_out[aa * 64 + t] * W_ih[(64 + t) * 192 + c];
            v = a;
        }
    } else if (k < 192) {
        int aa = k - 128;
        if (c < 128) v = W_hh[aa * 192 + c];
        else if (c >= 192) v = W_hh[aa * 192 + 128 + (c - 192)];
    } else if (k == 192) {
        if (c < 192) {
            float a = 0.f;
            for (int t = 0; t < 64; t++) a += b_in[t] * W_ih[t * 192 + c];
            v = a;
        }
    } else if (k == 193) {
        if (c < 192) {
            float a = 0.f;
            for (int t = 0; t < 64; t++) a += b_out[t] * W_ih[(64 + t) * 192 + c];
            v = a;
        }
    }
    g_M[k * C_TOT + c] = v;
    if (k == 0) {
        float b;
        if (c < 128)      b = b_ih[c] + b_hh[c];
        else if (c < 192) b = b_ih[c];
        else              b = b_hh[c - 64];
        g_bias[c] = b;
    }
}

// ---------------- CSR build ----------------
__global__ void zero_cnt_kernel(int nseg) {
    int i = blockIdx.x * blockDim.x + threadIdx.x;
    if (i < nseg) g_cnt[i] = 0;
}

__global__ void hist_kernel(const int* __restrict__ dstA, const int* __restrict__ dstB,
                            int E, int n) {
    int set = blockIdx.y;
    const int* dst = set ? dstB : dstA;
    int base = set * n;
    for (int e = blockIdx.x * blockDim.x + threadIdx.x; e < E; e += gridDim.x * blockDim.x)
        atomicAdd(&g_cnt[base + dst[e]], 1);
}

__global__ void scan1_kernel(int nseg) {
    __shared__ int sh[1024];
    int tid = threadIdx.x;
    int g = blockIdx.x * 1024 + tid;
    int x = (g < nseg) ? g_cnt[g] : 0;
    sh[tid] = x;
    __syncthreads();
    #pragma unroll
    for (int o = 1; o < 1024; o <<= 1) {
        int v = (tid >= o) ? sh[tid - o] : 0;
        __syncthreads();
        sh[tid] += v;
        __syncthreads();
    }
    if (g < nseg) g_off[g] = sh[tid] - x;     // exclusive
    if (tid == 1023) g_bsum[blockIdx.x] = sh[1023];
}

// parallel exclusive scan over <=256 block sums (single block)
__global__ void scan2_kernel(int nblocks) {
    __shared__ int sh[256];
    int tid = threadIdx.x;
    int x = (tid < nblocks) ? g_bsum[tid] : 0;
    sh[tid] = x;
    __syncthreads();
    #pragma unroll
    for (int o = 1; o < 256; o <<= 1) {
        int v = (tid >= o) ? sh[tid - o] : 0;
        __syncthreads();
        sh[tid] += v;
        __syncthreads();
    }
    if (tid < nblocks) g_bsum[tid] = sh[tid] - x;   // exclusive
}

__global__ void scan3_kernel(int nseg) {
    int g = blockIdx.x * 1024 + threadIdx.x;
    if (g < nseg) g_off[g] += g_bsum[blockIdx.x];
}

__global__ void fill_kernel(const int* __restrict__ srcA, const int* __restrict__ dstA,
                            const float* __restrict__ wA,
                            const int* __restrict__ srcB, const int* __restrict__ dstB,
                            const float* __restrict__ wB,
                            int E, int n) {
    int set = blockIdx.y;
    const int*   src = set ? srcB : srcA;
    const int*   dst = set ? dstB : dstA;
    const float* wp  = set ? wB   : wA;
    int base = set * n;
    for (int e = blockIdx.x * blockDim.x + threadIdx.x; e < E; e += gridDim.x * blockDim.x) {
        int pos = atomicAdd(&g_off[base + dst[e]], 1);
        g_csr[pos] = make_int2(src[e], __float_as_int(wp[e]));
    }
}

// ---------------- gather: atomic-free segment sums (R11-exact) ----------------
// Half-warp (16 lanes, float4 each) per segment; writes S and s directly.
__global__ void gather_kernel(const float4* __restrict__ h4, int nseg) {
    int l   = threadIdx.x & 15;
    int hw  = (blockIdx.x * blockDim.x + threadIdx.x) >> 4;
    int nhw = (gridDim.x * blockDim.x) >> 4;

    for (int s = hw; s < nseg; s += nhw) {
        int end = g_off[s];              // after fill: end of segment
        int cnt = g_cnt[s];
        int e = end - cnt;
        float4 acc = make_float4(0.f, 0.f, 0.f, 0.f);
        float ws = 0.f;
        #pragma unroll 2
        for (; e < end; e++) {
            int2 ed = g_csr[e];
            float w = __int_as_float(ed.y);
            float4 v = h4[(size_t)ed.x * 16 + l];
            acc.x += v.x * w; acc.y += v.y * w; acc.z += v.z * w; acc.w += v.w * w;
            ws += w;
        }
        reinterpret_cast<float4*>(g_S)[(size_t)s * 16 + l] = acc;
        if (l == 0) g_s[s] = ws;
    }
}

__device__ __forceinline__ float fsig(float x) { return 1.f / (1.f + __expf(-x)); }
__device__ __forceinline__ float ftanh(float x) { return 2.f / (1.f + __expf(-2.f * x)) - 1.f; }

// one k-step: 32 FFMA, 8 nodes x 4 cols
__device__ __forceinline__ void step84(float acc[8][4], const float* mp, const float* xp) {
    float4 m  = *reinterpret_cast<const float4*>(mp);
    float4 xa = *reinterpret_cast<const float4*>(xp);
    float4 xb = *reinterpret_cast<const float4*>(xp + 4);
    acc[0][0]+=xa.x*m.x; acc[0][1]+=xa.x*m.y; acc[0][2]+=xa.x*m.z; acc[0][3]+=xa.x*m.w;
    acc[1][0]+=xa.y*m.x; acc[1][1]+=xa.y*m.y; acc[1][2]+=xa.y*m.z; acc[1][3]+=xa.y*m.w;
    acc[2][0]+=xa.z*m.x; acc[2][1]+=xa.z*m.y; acc[2][2]+=xa.z*m.z; acc[2][3]+=xa.z*m.w;
    acc[3][0]+=xa.w*m.x; acc[3][1]+=xa.w*m.y; acc[3][2]+=xa.w*m.z; acc[3][3]+=xa.w*m.w;
    acc[4][0]+=xb.x*m.x; acc[4][1]+=xb.x*m.y; acc[4][2]+=xb.x*m.z; acc[4][3]+=xb.x*m.w;
    acc[5][0]+=xb.y*m.x; acc[5][1]+=xb.y*m.y; acc[5][2]+=xb.y*m.z; acc[5][3]+=xb.y*m.w;
    acc[6][0]+=xb.z*m.x; acc[6][1]+=xb.z*m.y; acc[6][2]+=xb.z*m.z; acc[6][3]+=xb.z*m.w;
    acc[7][0]+=xb.w*m.x; acc[7][1]+=xb.w*m.y; acc[7][2]+=xb.w*m.z; acc[7][3]+=xb.w*m.w;
}

// ---------------- node kernel (unchanged from R10) ----------------
extern __shared__ float smem[];

__global__ __launch_bounds__(NTHREADS, 1) void node_kernel(const float* __restrict__ hidden,
                                                           float* __restrict__ out,
                                                           int n_nodes, int ntiles) {
    float* Mg = smem + OFF_MG;
    float* Mi = smem + OFF_MI;
    float* Mh = smem + OFF_MH;
    float* UB = smem + OFF_UB;

    int tid = threadIdx.x;
    int wid = tid >> 5;
    int lane = tid & 31;

    {
        float4* Mg4 = reinterpret_cast<float4*>(Mg);
        for (int i = tid; i < 194 * 32; i += NTHREADS) {
            int r = i >> 5, c4 = i & 31;
            Mg4[i] = *reinterpret_cast<const float4*>(&g_M[r * C_TOT + c4 * 4]);
        }
        float4* Mi4 = reinterpret_cast<float4*>(Mi);
        for (int i = tid; i < 130 * 16; i += NTHREADS) {
            int r = i >> 4, c4 = i & 15;
            int gr = (r < 128) ? r : (192 + (r - 128));
            Mi4[i] = *reinterpret_cast<const float4*>(&g_M[gr * C_TOT + 128 + c4 * 4]);
        }
        float4* Mh4 = reinterpret_cast<float4*>(Mh);
        for (int i = tid; i < 64 * 16; i += NTHREADS) {
            int r = i >> 4, c4 = i & 15;
            Mh4[i] = *reinterpret_cast<const float4*>(&g_M[(128 + r) * C_TOT + 192 + c4 * 4]);
        }
    }
    __syncthreads();

    const float* Sin  = g_S;
    const float* Sout = g_S + (size_t)n_nodes * D;

    int kh, ng, colb;
    if (wid < 16)      { kh = wid >> 3;        ng = wid & 7;                        colb = lane * 4; }
    else if (wid < 24) { kh = (wid - 16) >> 2; ng = ((wid - 16) & 3) * 2 + (lane >> 4); colb = 128 + (lane & 15) * 4; }
    else               { kh = (wid - 24) >> 2; ng = ((wid - 24) & 3) * 2 + (lane >> 4); colb = 192 + (lane & 15) * 4; }

    for (int tile = blockIdx.x; tile < ntiles; tile += gridDim.x) {
        int node0 = tile * TILE_N;

        {
            int g = tid >> 4;
            int l = tid & 15;
            int n = node0 + g;
            bool nv = (n < n_nodes);
            #pragma unroll
            for (int k = l; k < 194; k += 16) {
                float v = 0.f;
                if (nv) {
                    if (k < 64)        v = Sin[(size_t)n * D + k];
                    else if (k < 128)  v = Sout[(size_t)n * D + (k - 64)];
                    else if (k < 192)  v = hidden[(size_t)n * D + (k - 128)];
                    else if (k == 192) v = g_s[n];
                    else               v = g_s[n_nodes + n];
                }
                UB[k * XSTR + g] = v;
            }
        }
        __syncthreads();

        float acc[8][4];
        if (kh == 0) {
            float4 bv = *reinterpret_cast<const float4*>(&g_bias[colb]);
            #pragma unroll
            for (int i = 0; i < 8; i++) { acc[i][0]=bv.x; acc[i][1]=bv.y; acc[i][2]=bv.z; acc[i][3]=bv.w; }
        } else {
            #pragma unroll
            for (int i = 0; i < 8; i++) { acc[i][0]=0.f; acc[i][1]=0.f; acc[i][2]=0.f; acc[i][3]=0.f; }
        }

        if (wid < 16) {
            const float* mp = Mg + (kh * 97) * 128 + colb;
            const float* xp = UB + (kh * 97) * XSTR + ng * 8;
            #pragma unroll 2
            for (int k = 0; k < 97; k++) {
                step84(acc, mp, xp);
                mp += 128; xp += XSTR;
            }
        } else if (wid < 24) {
            if (kh == 0) {
                const float* mp = Mi + (colb - 128);
                const float* xp = UB + ng * 8;
                #pragma unroll 2
                for (int k = 0; k < 65; k++) {
                    step84(acc, mp, xp);
                    mp += 64; xp += XSTR;
                }
            } else {
                const float* mp = Mi + 65 * 64 + (colb - 128);
                const float* xp = UB + 65 * XSTR + ng * 8;
                #pragma unroll 2
                for (int k = 0; k < 63; k++) {
                    step84(acc, mp, xp);
                    mp += 64; xp += XSTR;
                }
                step84(acc, mp, UB + 192 * XSTR + ng * 8);
                step84(acc, mp + 64, UB + 193 * XSTR + ng * 8);
            }
        } else {
            const float* mp = Mh + (kh * 32) * 64 + (colb - 192);
            const float* xp = UB + (128 + kh * 32) * XSTR + ng * 8;
            #pragma unroll 2
            for (int k = 0; k < 32; k++) {
                step84(acc, mp, xp);
                mp += 64; xp += XSTR;
            }
        }
        __syncthreads();

        if (kh == 1) {
            #pragma unroll
            for (int i = 0; i < 8; i++)
                *reinterpret_cast<float4*>(&UB[(ng * 8 + i) * C_TOT + colb]) =
                    make_float4(acc[i][0], acc[i][1], acc[i][2], acc[i][3]);
        }
        __syncthreads();
        if (kh == 0) {
            #pragma unroll
            for (int i = 0; i < 8; i++) {
                float4* p = reinterpret_cast<float4*>(&UB[(ng * 8 + i) * C_TOT + colb]);
                float4 v = *p;
                v.x += acc[i][0]; v.y += acc[i][1]; v.z += acc[i][2]; v.w += acc[i][3];
                *p = v;
            }
        }
        __syncthreads();

        #pragma unroll
        for (int j = 0; j < 4; j++) {
            int o = tid + j * NTHREADS;
            int i = o >> 6;
            int a = o & 63;
            int n = node0 + i;
            if (n < n_nodes) {
                float gr   = UB[i * C_TOT + a];
                float gi   = UB[i * C_TOT + 64 + a];
                float g_in = UB[i * C_TOT + 128 + a];
                float g_hn = UB[i * C_TOT + 192 + a];
                float r  = fsig(gr);
                float ig = fsig(gi);
                float newg = ftanh(g_in + r * g_hn);
                float h = hidden[(size_t)n * D + a];
                out[(size_t)n * D + a] = (1.f - ig) * h + ig * newg;
            }
        }
        __syncthreads();
    }
}

// ---------------- launch ----------------
extern "C" void kernel_launch(void* const* d_in, const int* in_sizes, int n_in,
                              void* d_out, int out_size) {
    const float* hidden  = (const float*)d_in[0];
    const int*   in_src  = (const int*)  d_in[1];
    const int*   in_dst  = (const int*)  d_in[2];
    const float* in_w    = (const float*)d_in[3];
    const int*   out_src = (const int*)  d_in[4];
    const int*   out_dst = (const int*)  d_in[5];
    const float* out_w   = (const float*)d_in[6];
    const float* W_in    = (const float*)d_in[7];
    const float* b_in    = (const float*)d_in[8];
    const float* W_out   = (const float*)d_in[9];
    const float* b_out   = (const float*)d_in[10];
    const float* W_ih    = (const float*)d_in[11];
    const float* b_ih    = (const float*)d_in[12];
    const float* W_hh    = (const float*)d_in[13];
    const float* b_hh    = (const float*)d_in[14];
    float* out = (float*)d_out;

    int n = in_sizes[0] / D;
    if (n > MAXN) n = MAXN;
    int E = in_sizes[1];
    if (E > MAXE) E = MAXE;

    int nseg = 2 * n;
    int sblk = (nseg + 1023) / 1024;     // <= 196

    precompute_kernel<<<K_PAD, C_TOT>>>(W_in, b_in, W_out, b_out, W_ih, b_ih, W_hh, b_hh);

    // CSR build
    zero_cnt_kernel<<<sblk, 1024>>>(nseg);
    if (E > 0) {
        dim3 hgrid(592, 2);
        hist_kernel<<<hgrid, 256>>>(in_dst, out_dst, E, n);
    }
    scan1_kernel<<<sblk, 1024>>>(nseg);
    scan2_kernel<<<1, 256>>>(sblk);
    scan3_kernel<<<sblk, 1024>>>(nseg);
    if (E > 0) {
        dim3 fgrid(592, 2);
        fill_kernel<<<fgrid, 256>>>(in_src, in_dst, in_w, out_src, out_dst, out_w, E, n);
    }

    // atomic-free gather
    gather_kernel<<<1184, 256>>>((const float4*)hidden, nseg);

    // fused node GEMM + GRU
    int ntiles = (n + TILE_N - 1) / TILE_N;
    int grid_n = ntiles < GRID_SM ? ntiles : GRID_SM;
    size_t smem_bytes = (size_t)SMEM_FLOATS * sizeof(float);
    cudaFuncSetAttribute(node_kernel, cudaFuncAttributeMaxDynamicSharedMemorySize,
                         (int)smem_bytes);
    node_kernel<<<grid_n, NTHREADS, smem_bytes>>>(hidden, out, n, ntiles);
}

// round 17
// speedup vs baseline: 1.3213x; 1.2243x over previous
#include <cuda_runtime.h>
#include <cuda_bf16.h>
#include <math.h>
#include <stdint.h>

#define MAXN 100000
#define MAXE 1600000
#define D 64
#define K_PAD 208
#define C_TOT 256      // cols: [0:64) r, [64:128) i, [128:192) i_n, [192:256) h_n
#define TW 64          // nodes per CTA tile
#define NTH 512
#define GRID_SM 148
#define BSTR 216       // Mt row stride in bf16 (216*2=432B -> conflict-free B frags)
#define SM_BYTES (2 * 256 * BSTR * 2)   // 221,184 B

// ---------------- scratch ----------------
__device__ float g_S[2 * (size_t)MAXN * D];
__device__ float g_s[2 * MAXN];
__device__ float g_M[K_PAD * C_TOT];
__device__ float g_bias[C_TOT];
__device__ int   g_cnt[2 * MAXN];
__device__ int   g_off[2 * MAXN];
__device__ int   g_bsum[256];
__device__ int2  g_csr[2 * (size_t)MAXE];
__device__ __align__(16) __nv_bfloat16 g_BtH[256 * BSTR];  // Mt hi: [col][k]
__device__ __align__(16) __nv_bfloat16 g_BtL[256 * BSTR];  // Mt lo

// ---------------- helpers ----------------
__device__ __forceinline__ uint32_t pkbf(float lo, float hi) {
    uint32_t r;
    asm("cvt.rn.bf16x2.f32 %0, %1, %2;" : "=r"(r) : "f"(hi), "f"(lo));
    return r;
}
// split float2 -> bf16x2 hi + bf16x2 lo
__device__ __forceinline__ void split2(float2 p, uint32_t& h, uint32_t& l) {
    h = pkbf(p.x, p.y);
    float h0 = __uint_as_float(h << 16);
    float h1 = __uint_as_float(h & 0xFFFF0000u);
    l = pkbf(p.x - h0, p.y - h1);
}

#define MMA16816(dp, A0, A1, A2, A3, B0, B1) \
    asm volatile("mma.sync.aligned.m16n8k16.row.col.f32.bf16.bf16.f32 " \
        "{%0,%1,%2,%3}, {%4,%5,%6,%7}, {%8,%9}, {%0,%1,%2,%3};" \
        : "+f"((dp)[0]), "+f"((dp)[1]), "+f"((dp)[2]), "+f"((dp)[3]) \
        : "r"(A0), "r"(A1), "r"(A2), "r"(A3), "r"(B0), "r"(B1))

__device__ __forceinline__ float fsig(float x) { return 1.f / (1.f + __expf(-x)); }
__device__ __forceinline__ float ftanh(float x) { return 2.f / (1.f + __expf(-2.f * x)) - 1.f; }

// ---------------- kernel 1: precompute fused matrix ----------------
__global__ void precompute_kernel(const float* __restrict__ W_in, const float* __restrict__ b_in,
                                  const float* __restrict__ W_out, const float* __restrict__ b_out,
                                  const float* __restrict__ W_ih, const float* __restrict__ b_ih,
                                  const float* __restrict__ W_hh, const float* __restrict__ b_hh) {
    int k = blockIdx.x;
    int c = threadIdx.x;
    float v = 0.f;
    if (k < 64) {
        if (c < 192) {
            float a = 0.f;
            #pragma unroll 8
            for (int t = 0; t < 64; t++) a += W_in[k * 64 + t] * W_ih[t * 192 + c];
            v = a;
        }
    } else if (k < 128) {
        if (c < 192) {
            int aa = k - 64;
            float a = 0.f;
            #pragma unroll 8
            for (int t = 0; t < 64; t++) a += W_out[aa * 64 + t] * W_ih[(64 + t) * 192 + c];
            v = a;
        }
    } else if (k < 192) {
        int aa = k - 128;
        if (c < 128) v = W_hh[aa * 192 + c];
        else if (c >= 192) v = W_hh[aa * 192 + 128 + (c - 192)];
    } else if (k == 192) {
        if (c < 192) {
            float a = 0.f;
            for (int t = 0; t < 64; t++) a += b_in[t] * W_ih[t * 192 + c];
            v = a;
        }
    } else if (k == 193) {
        if (c < 192) {
            float a = 0.f;
            for (int t = 0; t < 64; t++) a += b_out[t] * W_ih[(64 + t) * 192 + c];
            v = a;
        }
    }
    g_M[k * C_TOT + c] = v;
    if (k == 0) {
        float b;
        if (c < 128)      b = b_ih[c] + b_hh[c];
        else if (c < 192) b = b_ih[c];
        else              b = b_hh[c - 64];
        g_bias[c] = b;
    }
}

// ---------------- kernel 1b: transposed bf16 hi/lo panels Mt[c][k] ----------------
__global__ void bpanT_kernel() {
    int c = blockIdx.x;          // 0..255
    int k = threadIdx.x;         // 0..215
    float v = (k < K_PAD) ? g_M[k * C_TOT + c] : 0.f;
    __nv_bfloat16 hi = __float2bfloat16(v);
    float hf = __bfloat162float(hi);
    __nv_bfloat16 lo = __float2bfloat16(v - hf);
    g_BtH[c * BSTR + k] = hi;
    g_BtL[c * BSTR + k] = lo;
}

// ---------------- CSR build (R14-exact) ----------------
__global__ void zero_cnt_kernel(int nseg) {
    int i = blockIdx.x * blockDim.x + threadIdx.x;
    if (i < nseg) g_cnt[i] = 0;
}

__global__ void hist_kernel(const int* __restrict__ dstA, const int* __restrict__ dstB,
                            int E, int n) {
    int set = blockIdx.y;
    const int* dst = set ? dstB : dstA;
    int base = set * n;
    for (int e = blockIdx.x * blockDim.x + threadIdx.x; e < E; e += gridDim.x * blockDim.x)
        atomicAdd(&g_cnt[base + dst[e]], 1);
}

__global__ void scan1_kernel(int nseg) {
    __shared__ int sh[1024];
    int tid = threadIdx.x;
    int g = blockIdx.x * 1024 + tid;
    int x = (g < nseg) ? g_cnt[g] : 0;
    sh[tid] = x;
    __syncthreads();
    #pragma unroll
    for (int o = 1; o < 1024; o <<= 1) {
        int v = (tid >= o) ? sh[tid - o] : 0;
        __syncthreads();
        sh[tid] += v;
        __syncthreads();
    }
    if (g < nseg) g_off[g] = sh[tid] - x;
    if (tid == 1023) g_bsum[blockIdx.x] = sh[1023];
}

__global__ void scan2_kernel(int nblocks) {
    __shared__ int sh[256];
    int tid = threadIdx.x;
    int x = (tid < nblocks) ? g_bsum[tid] : 0;
    sh[tid] = x;
    __syncthreads();
    #pragma unroll
    for (int o = 1; o < 256; o <<= 1) {
        int v = (tid >= o) ? sh[tid - o] : 0;
        __syncthreads();
        sh[tid] += v;
        __syncthreads();
    }
    if (tid < nblocks) g_bsum[tid] = sh[tid] - x;
}

__global__ void scan3_kernel(int nseg) {
    int g = blockIdx.x * 1024 + threadIdx.x;
    if (g < nseg) g_off[g] += g_bsum[blockIdx.x];
}

__global__ void fill_kernel(const int* __restrict__ srcA, const int* __restrict__ dstA,
                            const float* __restrict__ wA,
                            const int* __restrict__ srcB, const int* __restrict__ dstB,
                            const float* __restrict__ wB,
                            int E, int n) {
    int set = blockIdx.y;
    const int*   src = set ? srcB : srcA;
    const int*   dst = set ? dstB : dstA;
    const float* wp  = set ? wB   : wA;
    int base = set * n;
    for (int e = blockIdx.x * blockDim.x + threadIdx.x; e < E; e += gridDim.x * blockDim.x) {
        int pos = atomicAdd(&g_off[base + dst[e]], 1);
        g_csr[pos] = make_int2(src[e], __float_as_int(wp[e]));
    }
}

__global__ void gather_kernel(const float4* __restrict__ h4, int nseg) {
    int l   = threadIdx.x & 15;
    int hw  = (blockIdx.x * blockDim.x + threadIdx.x) >> 4;
    int nhw = (gridDim.x * blockDim.x) >> 4;

    for (int s = hw; s < nseg; s += nhw) {
        int end = g_off[s];
        int cnt = g_cnt[s];
        int e = end - cnt;
        float4 acc = make_float4(0.f, 0.f, 0.f, 0.f);
        float ws = 0.f;
        #pragma unroll 2
        for (; e < end; e++) {
            int2 ed = g_csr[e];
            float w = __int_as_float(ed.y);
            float4 v = h4[(size_t)ed.x * 16 + l];
            acc.x += v.x * w; acc.y += v.y * w; acc.z += v.z * w; acc.w += v.w * w;
            ws += w;
        }
        reinterpret_cast<float4*>(g_S)[(size_t)s * 16 + l] = acc;
        if (l == 0) g_s[s] = ws;
    }
}

// ---------------- node kernel: mma.sync bf16x3 GEMM + register GRU ----------------
// 148 CTAs x 512 threads persistent. Mt hi/lo resident in smem.
// Warp (16 of them): ng = wid&3 -> nodes [tile*64 + ng*16, +16); cg = wid>>2 -> cols c0=cg*16
// Warp computes, for its 16 nodes, cols {q*64 + c0 + [0,16)} for ALL quadrants q=0..3.
// Fragments: A row-major m16k16 from global X rows; B col-major from smem Mt[c][k].
extern __shared__ __nv_bfloat16 smem_bf[];

__global__ __launch_bounds__(NTH, 1) void node_kernel(const float* __restrict__ hidden,
                                                      float* __restrict__ out,
                                                      int n_nodes, int ntiles) {
    __nv_bfloat16* MtH = smem_bf;
    __nv_bfloat16* MtL = smem_bf + 256 * BSTR;

    int tid = threadIdx.x;
    int wid = tid >> 5;
    int lane = tid & 31;
    int gg = lane >> 2;        // 0..7 (row group / B col group)
    int t2 = (lane & 3) * 2;   // k pair offset

    // ---- load Mt panels into smem ----
    {
        const uint4* sH = reinterpret_cast<const uint4*>(g_BtH);
        const uint4* sL = reinterpret_cast<const uint4*>(g_BtL);
        uint4* dH = reinterpret_cast<uint4*>(MtH);
        uint4* dL = reinterpret_cast<uint4*>(MtL);
        for (int i = tid; i < 256 * BSTR / 8; i += NTH) { dH[i] = sH[i]; dL[i] = sL[i]; }
    }
    __syncthreads();

    const float* Sin  = g_S;
    const float* Sout = g_S + (size_t)n_nodes * D;

    int ng = wid & 3;
    int c0 = (wid >> 2) * 16;

    // B smem byte offsets for the 8 (q,f) fragments (fixed per thread)
    uint32_t boff[8];
    #pragma unroll
    for (int q = 0; q < 4; q++)
        #pragma unroll
        for (int f = 0; f < 2; f++) {
            int col = q * 64 + c0 + f * 8 + gg;
            boff[q * 2 + f] = (uint32_t)(col * BSTR + t2) * 2u;
        }

    // bias values for acc init (per lane, per (q,f)): cols base+t2, base+t2+1
    float2 bias[8];
    #pragma unroll
    for (int q = 0; q < 4; q++)
        #pragma unroll
        for (int f = 0; f < 2; f++)
            bias[q * 2 + f] = *reinterpret_cast<const float2*>(&g_bias[q * 64 + c0 + f * 8 + t2]);

    for (int tile = blockIdx.x; tile < ntiles; tile += gridDim.x) {
        int m0 = tile * TW + ng * 16;
        int m_lo = m0 + gg;
        int m_hi = m_lo + 8;
        bool v_lo = (m_lo < n_nodes);
        bool v_hi = (m_hi < n_nodes);

        float acc[8][4];
        #pragma unroll
        for (int i = 0; i < 8; i++) {
            acc[i][0] = bias[i].x; acc[i][1] = bias[i].y;
            acc[i][2] = bias[i].x; acc[i][3] = bias[i].y;
        }

        #pragma unroll 1
        for (int kc = 0; kc < 13; kc++) {
            // ---- build A hi/lo fragments from global ----
            uint32_t ah0, ah1, ah2, ah3, al0, al1, al2, al3;
            if (kc < 12) {
                const float* pl;
                const float* ph;
                if (kc < 4)      { pl = Sin  + (size_t)m_lo * D + kc * 16;       ph = Sin  + (size_t)m_hi * D + kc * 16; }
                else if (kc < 8) { pl = Sout + (size_t)m_lo * D + (kc - 4) * 16; ph = Sout + (size_t)m_hi * D + (kc - 4) * 16; }
                else             { pl = hidden + (size_t)m_lo * D + (kc - 8) * 16; ph = hidden + (size_t)m_hi * D + (kc - 8) * 16; }
                float2 z = make_float2(0.f, 0.f);
                float2 q0 = v_lo ? *reinterpret_cast<const float2*>(pl + t2)     : z;
                float2 q1 = v_lo ? *reinterpret_cast<const float2*>(pl + t2 + 8) : z;
                float2 r0 = v_hi ? *reinterpret_cast<const float2*>(ph + t2)     : z;
                float2 r1 = v_hi ? *reinterpret_cast<const float2*>(ph + t2 + 8) : z;
                split2(q0, ah0, al0);
                split2(r0, ah1, al1);
                split2(q1, ah2, al2);
                split2(r1, ah3, al3);
            } else {
                // k 192..207: k192=s_in, k193=s_out, rest zero -> only t2==0 nonzero
                float2 z = make_float2(0.f, 0.f);
                float2 q0 = (t2 == 0 && v_lo) ? make_float2(g_s[m_lo], g_s[n_nodes + m_lo]) : z;
                float2 r0 = (t2 == 0 && v_hi) ? make_float2(g_s[m_hi], g_s[n_nodes + m_hi]) : z;
                split2(q0, ah0, al0);
                split2(r0, ah1, al1);
                ah2 = al2 = ah3 = al3 = 0u;
            }

            uint32_t kb = (uint32_t)(kc * 32);   // 16 k * 2B

            // ---- B hi fragments + 2 passes (Ah*Bh, Al*Bh) ----
            uint32_t bh0[8], bh1[8];
            #pragma unroll
            for (int i = 0; i < 8; i++) {
                const char* p = reinterpret_cast<const char*>(MtH) + boff[i] + kb;
                bh0[i] = *reinterpret_cast<const uint32_t*>(p);
                bh1[i] = *reinterpret_cast<const uint32_t*>(p + 16);
            }
            #pragma unroll
            for (int i = 0; i < 8; i++) MMA16816(acc[i], ah0, ah1, ah2, ah3, bh0[i], bh1[i]);
            #pragma unroll
            for (int i = 0; i < 8; i++) MMA16816(acc[i], al0, al1, al2, al3, bh0[i], bh1[i]);

            // ---- B lo fragments + pass (Ah*Bl) ----
            #pragma unroll
            for (int i = 0; i < 8; i++) {
                const char* p = reinterpret_cast<const char*>(MtL) + boff[i] + kb;
                bh0[i] = *reinterpret_cast<const uint32_t*>(p);
                bh1[i] = *reinterpret_cast<const uint32_t*>(p + 16);
            }
            #pragma unroll
            for (int i = 0; i < 8; i++) MMA16816(acc[i], ah0, ah1, ah2, ah3, bh0[i], bh1[i]);
        }

        // ---- GRU epilogue, fully in registers ----
        #pragma unroll
        for (int f = 0; f < 2; f++) {
            int a = c0 + f * 8 + t2;    // dim within [0,64), covers a and a+1
            #pragma unroll
            for (int rsel = 0; rsel < 2; rsel++) {
                int node = rsel ? m_hi : m_lo;
                if (node < n_nodes) {
                    float2 h2 = *reinterpret_cast<const float2*>(&hidden[(size_t)node * D + a]);
                    float2 o2;
                    #pragma unroll
                    for (int j = 0; j < 2; j++) {
                        float gr   = acc[0 + f][rsel * 2 + j];
                        float gi   = acc[2 + f][rsel * 2 + j];
                        float g_in = acc[4 + f][rsel * 2 + j];
                        float g_hn = acc[6 + f][rsel * 2 + j];
                        float r  = fsig(gr);
                        float ig = fsig(gi);
                        float newg = ftanh(g_in + r * g_hn);
                        float h = j ? h2.y : h2.x;
                        float hy = (1.f - ig) * h + ig * newg;
                        if (j) o2.y = hy; else o2.x = hy;
                    }
                    *reinterpret_cast<float2*>(&out[(size_t)node * D + a]) = o2;
                }
            }
        }
    }
}

// ---------------- launch ----------------
extern "C" void kernel_launch(void* const* d_in, const int* in_sizes, int n_in,
                              void* d_out, int out_size) {
    const float* hidden  = (const float*)d_in[0];
    const int*   in_src  = (const int*)  d_in[1];
    const int*   in_dst  = (const int*)  d_in[2];
    const float* in_w    = (const float*)d_in[3];
    const int*   out_src = (const int*)  d_in[4];
    const int*   out_dst = (const int*)  d_in[5];
    const float* out_w   = (const float*)d_in[6];
    const float* W_in    = (const float*)d_in[7];
    const float* b_in    = (const float*)d_in[8];
    const float* W_out   = (const float*)d_in[9];
    const float* b_out   = (const float*)d_in[10];
    const float* W_ih    = (const float*)d_in[11];
    const float* b_ih    = (const float*)d_in[12];
    const float* W_hh    = (const float*)d_in[13];
    const float* b_hh    = (const float*)d_in[14];
    float* out = (float*)d_out;

    int n = in_sizes[0] / D;
    if (n > MAXN) n = MAXN;
    int E = in_sizes[1];
    if (E > MAXE) E = MAXE;

    int nseg = 2 * n;
    int sblk = (nseg + 1023) / 1024;

    precompute_kernel<<<K_PAD, C_TOT>>>(W_in, b_in, W_out, b_out, W_ih, b_ih, W_hh, b_hh);
    bpanT_kernel<<<256, BSTR>>>();

    zero_cnt_kernel<<<sblk, 1024>>>(nseg);
    if (E > 0) {
        dim3 hgrid(592, 2);
        hist_kernel<<<hgrid, 256>>>(in_dst, out_dst, E, n);
    }
    scan1_kernel<<<sblk, 1024>>>(nseg);
    scan2_kernel<<<1, 256>>>(sblk);
    scan3_kernel<<<sblk, 1024>>>(nseg);
    if (E > 0) {
        dim3 fgrid(592, 2);
        fill_kernel<<<fgrid, 256>>>(in_src, in_dst, in_w, out_src, out_dst, out_w, E, n);
    }
    gather_kernel<<<1184, 256>>>((const float4*)hidden, nseg);

    int ntiles = (n + TW - 1) / TW;
    int grid_n = ntiles < GRID_SM ? ntiles : GRID_SM;
    cudaFuncSetAttribute(node_kernel, cudaFuncAttributeMaxDynamicSharedMemorySize, SM_BYTES);
    node_kernel<<<grid_n, NTH, SM_BYTES>>>(hidden, out, n, ntiles);
}